// round 15
// baseline (speedup 1.0000x reference)
#include <cuda_runtime.h>
#include <cuda_fp16.h>

#define Cc 10
#define Bb 512
#define Nn 1152
#define Ii 8
#define Oo 16

// Scratch u_hat[C,B,N,O] in fp16, stored as uint4 (8 halves per uint4) = 189 MB
__device__ uint4 g_uhat[(size_t)Cc * Bb * Nn * Oo / 8];

typedef unsigned long long u64;

// ---- packed f32x2 helpers (ptxas never auto-fuses these from C++) ----
__device__ __forceinline__ u64 fma2(u64 a, u64 b, u64 c) {
    u64 d; asm("fma.rn.f32x2 %0, %1, %2, %3;" : "=l"(d) : "l"(a), "l"(b), "l"(c)); return d;
}
__device__ __forceinline__ u64 mul2(u64 a, u64 b) {
    u64 d; asm("mul.rn.f32x2 %0, %1, %2;" : "=l"(d) : "l"(a), "l"(b)); return d;
}
__device__ __forceinline__ u64 add2(u64 a, u64 b) {
    u64 d; asm("add.rn.f32x2 %0, %1, %2;" : "=l"(d) : "l"(a), "l"(b)); return d;
}
__device__ __forceinline__ u64 dup2(float x) {
    u64 d; asm("mov.b64 %0, {%1, %1};" : "=l"(d) : "f"(x)); return d;
}
__device__ __forceinline__ u64 pack2(float lo, float hi) {
    u64 d; asm("mov.b64 %0, {%1, %2};" : "=l"(d) : "f"(lo), "f"(hi)); return d;
}
__device__ __forceinline__ void unpack2(u64 a, float& lo, float& hi) {
    asm("mov.b64 {%0, %1}, %2;" : "=f"(lo), "=f"(hi) : "l"(a));
}
__device__ __forceinline__ unsigned cvth2(float lo, float hi) {
    __half2 h = __floats2half2_rn(lo, hi);
    return *(unsigned*)&h;
}
__device__ __forceinline__ u64 h2f2(unsigned w) {
    __half2 h = *(__half2*)&w;
    float2 f = __half22float2(h);
    return pack2(f.x, f.y);
}

// ---------------------------------------------------------------------------
// Phase 1: u_hat[c,b,n,o] = sum_i u[b,n,i] * W[c,n,i,o], stored fp16.
// 256 thr = 128 n x 2 o-halves, W in 64 regs, 64-batch loop.
// Store policy: c < 6 streamed (.cs, evict-first); c >= 6 DEFAULT store so
// the last 75.5 MB of u_hat stays L2-resident for routing's reverse walk
// (R10/R12 fused runs proved normal stores pin u_hat in L2).
// Grid: (9, 8, 10) = 720 CTAs.
// ---------------------------------------------------------------------------
__global__ __launch_bounds__(256) void uhat_kernel(const float* __restrict__ u,
                                                   const float* __restrict__ W) {
    const int tid = threadIdx.x;
    const int n   = blockIdx.x * 128 + (tid >> 1);
    const int h   = tid & 1;
    const int b0  = blockIdx.y * 64;
    const int c   = blockIdx.z;

    u64 w2[8][4];
    const float* wc = W + (((size_t)c * Nn + n) * Ii) * Oo + h * 8;
#pragma unroll
    for (int i = 0; i < 8; i++) {
        ulonglong2 aa = *(const ulonglong2*)(wc + i * Oo);
        ulonglong2 bb = *(const ulonglong2*)(wc + i * Oo + 4);
        w2[i][0] = aa.x; w2[i][1] = aa.y; w2[i][2] = bb.x; w2[i][3] = bb.y;
    }

    const float* ub = u + ((size_t)b0 * Nn + n) * Ii;
    uint4* ob = g_uhat + (((size_t)c * Bb + b0) * Nn + n) * 2 + h;
    const bool keep_l2 = (c >= 6);

#pragma unroll 4
    for (int j = 0; j < 64; j++) {
        const float4* up = (const float4*)(ub + (size_t)j * (Nn * Ii));
        float4 a = __ldg(up);
        float4 b = __ldg(up + 1);
        float usv[8] = {a.x, a.y, a.z, a.w, b.x, b.y, b.z, b.w};

        u64 acc[4];
        {
            u64 ud = dup2(usv[0]);
#pragma unroll
            for (int k = 0; k < 4; k++) acc[k] = mul2(ud, w2[0][k]);
        }
#pragma unroll
        for (int i = 1; i < 8; i++) {
            u64 ud = dup2(usv[i]);
#pragma unroll
            for (int k = 0; k < 4; k++) acc[k] = fma2(ud, w2[i][k], acc[k]);
        }
        float r[8];
#pragma unroll
        for (int k = 0; k < 4; k++) unpack2(acc[k], r[2 * k], r[2 * k + 1]);

        uint4 st;
        st.x = cvth2(r[0], r[1]);
        st.y = cvth2(r[2], r[3]);
        st.z = cvth2(r[4], r[5]);
        st.w = cvth2(r[6], r[7]);
        if (keep_l2) ob[(size_t)j * (Nn * 2)] = st;       // keep in L2 for routing
        else         __stcs(ob + (size_t)j * (Nn * 2), st);  // stream to DRAM
    }
}

// ---------------------------------------------------------------------------
// Phase 2 (R14 verbatim): routing with split-butterfly S-reduce.
// 256-thr CTA per (c,b); slab in 72 f32 regs; reverse walk so the first
// ~40% of CTAs (c=9..6) read the L2-resident tail phase1 just wrote.
// ---------------------------------------------------------------------------
__global__ __launch_bounds__(256, 2) void routing_kernel(float* __restrict__ out) {
    const int tid  = threadIdx.x;
    const int b    = (Bb - 1) - blockIdx.x;
    const int c    = (Cc - 1) - blockIdx.y;
    const int lane = tid & 31, wid = tid >> 5;
    const int nl   = tid >> 1, h = tid & 1;

    __shared__ float red[8][17];  // [warp][o0..15, z]
    __shared__ float Vs[16];      // accumulated v

    // Load slab: one uint4 (8 fp16) per row per thread; convert once to f32x2.
    u64 uh[9][4];
    const uint4* p = g_uhat + ((size_t)c * Bb + b) * (size_t)(Nn * 2);
#pragma unroll
    for (int r = 0; r < 9; r++) {
        uint4 t = __ldcs(p + (size_t)(r * 128 + nl) * 2 + h);
        uh[r][0] = h2f2(t.x);
        uh[r][1] = h2f2(t.y);
        uh[r][2] = h2f2(t.z);
        uh[r][3] = h2f2(t.w);
    }

    const bool up1 = (lane >> 1) & 1;
    const bool up2 = (lane >> 2) & 1;
    const bool up3 = (lane >> 3) & 1;
    const int  o_of_lane = 8 * (lane & 1) + 4 * ((lane >> 1) & 1) +
                           2 * ((lane >> 2) & 1) + ((lane >> 3) & 1);

    for (int it = 0; it < 3; it++) {
        float S[8], z = 0.0f;
        u64 S2[4] = {0ull, 0ull, 0ull, 0ull};
        if (it == 0) {
#pragma unroll
            for (int r = 0; r < 9; r++)
#pragma unroll
                for (int k = 0; k < 4; k++) S2[k] = add2(S2[k], uh[r][k]);
        } else {
            u64 V2[4];
#pragma unroll
            for (int k = 0; k < 4; k++)
                V2[k] = pack2(Vs[8 * h + 2 * k], Vs[8 * h + 2 * k + 1]);
#pragma unroll
            for (int r = 0; r < 9; r++) {
                u64 d = mul2(uh[r][0], V2[0]);
                d = fma2(uh[r][1], V2[1], d);
                d = fma2(uh[r][2], V2[2], d);
                d = fma2(uh[r][3], V2[3], d);
                float lo, hi; unpack2(d, lo, hi);
                float a = lo + hi;
                a += __shfl_xor_sync(0xffffffffu, a, 1);  // partner o-half
                float e = __expf(a);
                z += e;
                u64 ed = dup2(e);
#pragma unroll
                for (int k = 0; k < 4; k++) S2[k] = fma2(ed, uh[r][k], S2[k]);
            }
        }
#pragma unroll
        for (int k = 0; k < 4; k++) unpack2(S2[k], S[2 * k], S[2 * k + 1]);

        // --- split-butterfly S-reduce over the 16 same-half lanes ---
        float v4[4];
#pragma unroll
        for (int k = 0; k < 4; k++) {
            float send = up1 ? S[k] : S[k + 4];
            float recv = __shfl_xor_sync(0xffffffffu, send, 2);
            v4[k] = (up1 ? S[k + 4] : S[k]) + recv;
        }
        float v2[2];
#pragma unroll
        for (int k = 0; k < 2; k++) {
            float send = up2 ? v4[k] : v4[k + 2];
            float recv = __shfl_xor_sync(0xffffffffu, send, 4);
            v2[k] = (up2 ? v4[k + 2] : v4[k]) + recv;
        }
        float v1;
        {
            float send = up3 ? v2[0] : v2[1];
            float recv = __shfl_xor_sync(0xffffffffu, send, 8);
            v1 = (up3 ? v2[1] : v2[0]) + recv;
        }
        v1 += __shfl_xor_sync(0xffffffffu, v1, 16);
        // v1 = S_total[o_of_lane], lanes 0..15 cover all o uniquely

        // z tree over the 16 same-parity lanes (it>0 only)
        if (it > 0) {
#pragma unroll
            for (int off = 2; off <= 16; off <<= 1)
                z += __shfl_xor_sync(0xffffffffu, z, off);
        }

        if (lane < 16) red[wid][o_of_lane] = v1;
        if (lane == 0) red[wid][16] = z;
        __syncthreads();

        // Final combine + squash: 16 threads, one per o
        if (tid < 16) {
            int o = tid;
            float s = 0.0f, Z = 0.0f;
#pragma unroll
            for (int w = 0; w < 8; w++) { s += red[w][o]; Z += red[w][16]; }
            if (it == 0) Z = (float)Nn;  // softmax of zeros: Z exactly N
            s /= Z;
            float sn = s * s;
#pragma unroll
            for (int off = 1; off <= 8; off <<= 1)
                sn += __shfl_xor_sync(0xffffu, sn, off);
            float fq = (sn / (1.0f + sn)) * rsqrtf(sn);
            float v = s * fq;
            if (it == 2) out[((size_t)c * Bb + b) * Oo + o] = v;
            else Vs[o] = (it == 0) ? v : (Vs[o] + v);
        }
        __syncthreads();
    }
}

// ---------------------------------------------------------------------------
extern "C" void kernel_launch(void* const* d_in, const int* in_sizes, int n_in,
                              void* d_out, int out_size) {
    const float* u = (const float*)d_in[0];  // [B,N,I]
    const float* W = (const float*)d_in[1];  // [C,N,I,O]
    float* out = (float*)d_out;              // [C,B,1,1,O]

    uhat_kernel<<<dim3(Nn / 128, Bb / 64, Cc), 256>>>(u, W);
    routing_kernel<<<dim3(Bb, Cc), 256>>>(out);
}

// round 16
// speedup vs baseline: 1.0037x; 1.0037x over previous
#include <cuda_runtime.h>
#include <cuda_fp16.h>

#define Cc 10
#define Bb 512
#define Nn 1152
#define Ii 8
#define Oo 16

// Scratch u_hat[C,B,N,O] in fp16, stored as uint4 (8 halves per uint4) = 189 MB
__device__ uint4 g_uhat[(size_t)Cc * Bb * Nn * Oo / 8];

typedef unsigned long long u64;

// ---- packed f32x2 helpers (ptxas never auto-fuses these from C++) ----
__device__ __forceinline__ u64 fma2(u64 a, u64 b, u64 c) {
    u64 d; asm("fma.rn.f32x2 %0, %1, %2, %3;" : "=l"(d) : "l"(a), "l"(b), "l"(c)); return d;
}
__device__ __forceinline__ u64 mul2(u64 a, u64 b) {
    u64 d; asm("mul.rn.f32x2 %0, %1, %2;" : "=l"(d) : "l"(a), "l"(b)); return d;
}
__device__ __forceinline__ u64 add2(u64 a, u64 b) {
    u64 d; asm("add.rn.f32x2 %0, %1, %2;" : "=l"(d) : "l"(a), "l"(b)); return d;
}
__device__ __forceinline__ u64 dup2(float x) {
    u64 d; asm("mov.b64 %0, {%1, %1};" : "=l"(d) : "f"(x)); return d;
}
__device__ __forceinline__ u64 pack2(float lo, float hi) {
    u64 d; asm("mov.b64 %0, {%1, %2};" : "=l"(d) : "f"(lo), "f"(hi)); return d;
}
__device__ __forceinline__ void unpack2(u64 a, float& lo, float& hi) {
    asm("mov.b64 {%0, %1}, %2;" : "=f"(lo), "=f"(hi) : "l"(a));
}
__device__ __forceinline__ unsigned cvth2(float lo, float hi) {
    __half2 h = __floats2half2_rn(lo, hi);
    return *(unsigned*)&h;
}
__device__ __forceinline__ u64 h2f2(unsigned w) {
    __half2 h = *(__half2*)&w;
    float2 f = __half22float2(h);
    return pack2(f.x, f.y);
}

// ---------------------------------------------------------------------------
// Phase 1 (R14 verbatim, all .cs -- measured ~54 us):
// u_hat[c,b,n,o] = sum_i u[b,n,i] * W[c,n,i,o], stored fp16.
// 256 thr = 128 n x 2 o-halves, W in 64 regs, 64-batch loop.
// Grid: (9, 8, 10) = 720 CTAs.
// ---------------------------------------------------------------------------
__global__ __launch_bounds__(256) void uhat_kernel(const float* __restrict__ u,
                                                   const float* __restrict__ W) {
    const int tid = threadIdx.x;
    const int n   = blockIdx.x * 128 + (tid >> 1);
    const int h   = tid & 1;
    const int b0  = blockIdx.y * 64;
    const int c   = blockIdx.z;

    u64 w2[8][4];
    const float* wc = W + (((size_t)c * Nn + n) * Ii) * Oo + h * 8;
#pragma unroll
    for (int i = 0; i < 8; i++) {
        ulonglong2 aa = *(const ulonglong2*)(wc + i * Oo);
        ulonglong2 bb = *(const ulonglong2*)(wc + i * Oo + 4);
        w2[i][0] = aa.x; w2[i][1] = aa.y; w2[i][2] = bb.x; w2[i][3] = bb.y;
    }

    const float* ub = u + ((size_t)b0 * Nn + n) * Ii;
    uint4* ob = g_uhat + (((size_t)c * Bb + b0) * Nn + n) * 2 + h;

#pragma unroll 4
    for (int j = 0; j < 64; j++) {
        const float4* up = (const float4*)(ub + (size_t)j * (Nn * Ii));
        float4 a = __ldg(up);
        float4 b = __ldg(up + 1);
        float usv[8] = {a.x, a.y, a.z, a.w, b.x, b.y, b.z, b.w};

        u64 acc[4];
        {
            u64 ud = dup2(usv[0]);
#pragma unroll
            for (int k = 0; k < 4; k++) acc[k] = mul2(ud, w2[0][k]);
        }
#pragma unroll
        for (int i = 1; i < 8; i++) {
            u64 ud = dup2(usv[i]);
#pragma unroll
            for (int k = 0; k < 4; k++) acc[k] = fma2(ud, w2[i][k], acc[k]);
        }
        float r[8];
#pragma unroll
        for (int k = 0; k < 4; k++) unpack2(acc[k], r[2 * k], r[2 * k + 1]);

        uint4 st;
        st.x = cvth2(r[0], r[1]);
        st.y = cvth2(r[2], r[3]);
        st.z = cvth2(r[4], r[5]);
        st.w = cvth2(r[6], r[7]);
        __stcs(ob + (size_t)j * (Nn * 2), st);
    }
}

// ---------------------------------------------------------------------------
// Phase 2: routing with the slab in SMEM instead of registers.
// cp.async stages 36 KB (fp16 slab) -> smem; passes read it via conflict-free
// LDS.128 (element index 256*r + tid is contiguous per warp) and convert
// h2 -> f32x2 on the fly. Data registers drop ~72 -> regs ~60, enabling
// launch_bounds(256,4): 4 CTAs/SM = 2x the load streams of R6/R14 (routing
// moved its mandatory 189 MB at only 34% of HBM = latency-bound).
// Reduction = R14 split-butterfly. Grid: (B, C), reverse walk.
// ---------------------------------------------------------------------------
__global__ __launch_bounds__(256, 4) void routing_kernel(float* __restrict__ out) {
    const int tid  = threadIdx.x;
    const int b    = (Bb - 1) - blockIdx.x;
    const int c    = (Cc - 1) - blockIdx.y;
    const int lane = tid & 31, wid = tid >> 5;
    const int h    = tid & 1;

    __shared__ uint4 slab[Nn * 2];   // 36864 B fp16 slab
    __shared__ float red[8][17];     // [warp][o0..15, z]
    __shared__ float Vs[16];         // accumulated v

    // Async stage: thread t copies elements 256*r + t (contiguous, coalesced).
    const uint4* p = g_uhat + ((size_t)c * Bb + b) * (size_t)(Nn * 2);
    {
        unsigned s0 = (unsigned)__cvta_generic_to_shared(slab + tid);
#pragma unroll
        for (int r = 0; r < 9; r++) {
            asm volatile("cp.async.cg.shared.global [%0], [%1], 16;"
                         :: "r"(s0 + r * 256 * 16), "l"(p + r * 256 + tid));
        }
        asm volatile("cp.async.commit_group;");
        asm volatile("cp.async.wait_group 0;" ::: "memory");
    }
    __syncthreads();

    const bool up1 = (lane >> 1) & 1;
    const bool up2 = (lane >> 2) & 1;
    const bool up3 = (lane >> 3) & 1;
    const int  o_of_lane = 8 * (lane & 1) + 4 * ((lane >> 1) & 1) +
                           2 * ((lane >> 2) & 1) + ((lane >> 3) & 1);

    for (int it = 0; it < 3; it++) {
        float S[8], z = 0.0f;
        u64 S2[4] = {0ull, 0ull, 0ull, 0ull};
        if (it == 0) {
#pragma unroll
            for (int r = 0; r < 9; r++) {
                uint4 t = slab[r * 256 + tid];
                S2[0] = add2(S2[0], h2f2(t.x));
                S2[1] = add2(S2[1], h2f2(t.y));
                S2[2] = add2(S2[2], h2f2(t.z));
                S2[3] = add2(S2[3], h2f2(t.w));
            }
        } else {
            u64 V2[4];
#pragma unroll
            for (int k = 0; k < 4; k++)
                V2[k] = pack2(Vs[8 * h + 2 * k], Vs[8 * h + 2 * k + 1]);
#pragma unroll
            for (int r = 0; r < 9; r++) {
                uint4 t = slab[r * 256 + tid];
                u64 f0 = h2f2(t.x), f1 = h2f2(t.y);
                u64 f2 = h2f2(t.z), f3 = h2f2(t.w);
                u64 d = mul2(f0, V2[0]);
                d = fma2(f1, V2[1], d);
                d = fma2(f2, V2[2], d);
                d = fma2(f3, V2[3], d);
                float lo, hi; unpack2(d, lo, hi);
                float a = lo + hi;
                a += __shfl_xor_sync(0xffffffffu, a, 1);  // partner o-half
                float e = __expf(a);
                z += e;
                u64 ed = dup2(e);
                S2[0] = fma2(ed, f0, S2[0]);
                S2[1] = fma2(ed, f1, S2[1]);
                S2[2] = fma2(ed, f2, S2[2]);
                S2[3] = fma2(ed, f3, S2[3]);
            }
        }
#pragma unroll
        for (int k = 0; k < 4; k++) unpack2(S2[k], S[2 * k], S[2 * k + 1]);

        // --- split-butterfly S-reduce over the 16 same-half lanes ---
        float v4[4];
#pragma unroll
        for (int k = 0; k < 4; k++) {
            float send = up1 ? S[k] : S[k + 4];
            float recv = __shfl_xor_sync(0xffffffffu, send, 2);
            v4[k] = (up1 ? S[k + 4] : S[k]) + recv;
        }
        float v2[2];
#pragma unroll
        for (int k = 0; k < 2; k++) {
            float send = up2 ? v4[k] : v4[k + 2];
            float recv = __shfl_xor_sync(0xffffffffu, send, 4);
            v2[k] = (up2 ? v4[k + 2] : v4[k]) + recv;
        }
        float v1;
        {
            float send = up3 ? v2[0] : v2[1];
            float recv = __shfl_xor_sync(0xffffffffu, send, 8);
            v1 = (up3 ? v2[1] : v2[0]) + recv;
        }
        v1 += __shfl_xor_sync(0xffffffffu, v1, 16);
        // v1 = S_total[o_of_lane], lanes 0..15 cover all o uniquely

        // z tree over the 16 same-parity lanes (it>0 only)
        if (it > 0) {
#pragma unroll
            for (int off = 2; off <= 16; off <<= 1)
                z += __shfl_xor_sync(0xffffffffu, z, off);
        }

        if (lane < 16) red[wid][o_of_lane] = v1;
        if (lane == 0) red[wid][16] = z;
        __syncthreads();

        // Final combine + squash: 16 threads, one per o
        if (tid < 16) {
            int o = tid;
            float s = 0.0f, Z = 0.0f;
#pragma unroll
            for (int w = 0; w < 8; w++) { s += red[w][o]; Z += red[w][16]; }
            if (it == 0) Z = (float)Nn;  // softmax of zeros: Z exactly N
            s /= Z;
            float sn = s * s;
#pragma unroll
            for (int off = 1; off <= 8; off <<= 1)
                sn += __shfl_xor_sync(0xffffu, sn, off);
            float fq = (sn / (1.0f + sn)) * rsqrtf(sn);
            float v = s * fq;
            if (it == 2) out[((size_t)c * Bb + b) * Oo + o] = v;
            else Vs[o] = (it == 0) ? v : (Vs[o] + v);
        }
        __syncthreads();
    }
}

// ---------------------------------------------------------------------------
extern "C" void kernel_launch(void* const* d_in, const int* in_sizes, int n_in,
                              void* d_out, int out_size) {
    const float* u = (const float*)d_in[0];  // [B,N,I]
    const float* W = (const float*)d_in[1];  // [C,N,I,O]
    float* out = (float*)d_out;              // [C,B,1,1,O]

    uhat_kernel<<<dim3(Nn / 128, Bb / 64, Cc), 256>>>(u, W);
    routing_kernel<<<dim3(Bb, Cc), 256>>>(out);
}

// round 17
// speedup vs baseline: 1.0936x; 1.0896x over previous
#include <cuda_runtime.h>
#include <cuda_fp16.h>

#define Cc 10
#define Bb 512
#define Nn 1152
#define Ii 8
#define Oo 16

// Scratch u_hat[C,B,N,O] in fp16, stored as uint4 (8 halves per uint4) = 189 MB
__device__ uint4 g_uhat[(size_t)Cc * Bb * Nn * Oo / 8];

typedef unsigned long long u64;

// ---- packed f32x2 helpers (ptxas never auto-fuses these from C++) ----
__device__ __forceinline__ u64 fma2(u64 a, u64 b, u64 c) {
    u64 d; asm("fma.rn.f32x2 %0, %1, %2, %3;" : "=l"(d) : "l"(a), "l"(b), "l"(c)); return d;
}
__device__ __forceinline__ u64 mul2(u64 a, u64 b) {
    u64 d; asm("mul.rn.f32x2 %0, %1, %2;" : "=l"(d) : "l"(a), "l"(b)); return d;
}
__device__ __forceinline__ u64 add2(u64 a, u64 b) {
    u64 d; asm("add.rn.f32x2 %0, %1, %2;" : "=l"(d) : "l"(a), "l"(b)); return d;
}
__device__ __forceinline__ u64 dup2(float x) {
    u64 d; asm("mov.b64 %0, {%1, %1};" : "=l"(d) : "f"(x)); return d;
}
__device__ __forceinline__ u64 pack2(float lo, float hi) {
    u64 d; asm("mov.b64 %0, {%1, %2};" : "=l"(d) : "f"(lo), "f"(hi)); return d;
}
__device__ __forceinline__ void unpack2(u64 a, float& lo, float& hi) {
    asm("mov.b64 {%0, %1}, %2;" : "=f"(lo), "=f"(hi) : "l"(a));
}
__device__ __forceinline__ unsigned cvth2(float lo, float hi) {
    __half2 h = __floats2half2_rn(lo, hi);
    return *(unsigned*)&h;
}
__device__ __forceinline__ u64 h2f2(unsigned w) {
    __half2 h = *(__half2*)&w;
    float2 f = __half22float2(h);
    return pack2(f.x, f.y);
}

// ---------------------------------------------------------------------------
// Phase 1: u_hat[c,b,n,o] = sum_i u[b,n,i] * W[c,n,i,o], stored fp16.
// C-PAIR VARIANT: each CTA covers TWO consecutive c with a 32-batch j-loop.
// The 128 KB u tile fits L1, so the second c-pass re-reads u from L1 and the
// u L2 traffic (~halved: 184 -> ~100 MB) drops phase1 below the LTS cap.
// Grid stays at 720 CTAs (9 n-blocks x 16 b-slices x 5 c-pairs) -- the R8
// lesson: don't shrink TLP.
// ---------------------------------------------------------------------------
__global__ __launch_bounds__(256) void uhat_kernel(const float* __restrict__ u,
                                                   const float* __restrict__ W) {
    const int tid   = threadIdx.x;
    const int n     = blockIdx.x * 128 + (tid >> 1);
    const int h     = tid & 1;
    const int b0    = blockIdx.y * 32;
    const int cbase = blockIdx.z * 2;

    const float* ub = u + ((size_t)b0 * Nn + n) * Ii;

#pragma unroll
    for (int cc = 0; cc < 2; cc++) {
        const int c = cbase + cc;

        // W[c,n,i, 8h..8h+7] as packed f32 pairs (64 regs)
        u64 w2[8][4];
        const float* wc = W + (((size_t)c * Nn + n) * Ii) * Oo + h * 8;
#pragma unroll
        for (int i = 0; i < 8; i++) {
            ulonglong2 aa = *(const ulonglong2*)(wc + i * Oo);
            ulonglong2 bb = *(const ulonglong2*)(wc + i * Oo + 4);
            w2[i][0] = aa.x; w2[i][1] = aa.y; w2[i][2] = bb.x; w2[i][3] = bb.y;
        }

        uint4* ob = g_uhat + (((size_t)c * Bb + b0) * Nn + n) * 2 + h;

#pragma unroll 4
        for (int j = 0; j < 32; j++) {
            const float4* up = (const float4*)(ub + (size_t)j * (Nn * Ii));
            float4 a = __ldg(up);        // L1-cached; cc=1 pass hits L1
            float4 b = __ldg(up + 1);
            float usv[8] = {a.x, a.y, a.z, a.w, b.x, b.y, b.z, b.w};

            u64 acc[4];
            {
                u64 ud = dup2(usv[0]);
#pragma unroll
                for (int k = 0; k < 4; k++) acc[k] = mul2(ud, w2[0][k]);
            }
#pragma unroll
            for (int i = 1; i < 8; i++) {
                u64 ud = dup2(usv[i]);
#pragma unroll
                for (int k = 0; k < 4; k++) acc[k] = fma2(ud, w2[i][k], acc[k]);
            }
            float r[8];
#pragma unroll
            for (int k = 0; k < 4; k++) unpack2(acc[k], r[2 * k], r[2 * k + 1]);

            uint4 st;
            st.x = cvth2(r[0], r[1]);
            st.y = cvth2(r[2], r[3]);
            st.z = cvth2(r[4], r[5]);
            st.w = cvth2(r[6], r[7]);
            __stcs(ob + (size_t)j * (Nn * 2), st);
        }
    }
}

// ---------------------------------------------------------------------------
// Phase 2 (R16 verbatim -- ncu-measured 58.2 us, occ 47%, issue 60%):
// slab staged to SMEM via cp.async, read back as conflict-free LDS.128,
// h2 -> f32x2 on the fly; split-butterfly S-reduce; launch_bounds(256,4).
// Grid: (B, C), reverse walk.
// ---------------------------------------------------------------------------
__global__ __launch_bounds__(256, 4) void routing_kernel(float* __restrict__ out) {
    const int tid  = threadIdx.x;
    const int b    = (Bb - 1) - blockIdx.x;
    const int c    = (Cc - 1) - blockIdx.y;
    const int lane = tid & 31, wid = tid >> 5;
    const int h    = tid & 1;

    __shared__ uint4 slab[Nn * 2];   // 36864 B fp16 slab
    __shared__ float red[8][17];     // [warp][o0..15, z]
    __shared__ float Vs[16];         // accumulated v

    // Async stage: thread t copies elements 256*r + t (contiguous, coalesced).
    const uint4* p = g_uhat + ((size_t)c * Bb + b) * (size_t)(Nn * 2);
    {
        unsigned s0 = (unsigned)__cvta_generic_to_shared(slab + tid);
#pragma unroll
        for (int r = 0; r < 9; r++) {
            asm volatile("cp.async.cg.shared.global [%0], [%1], 16;"
                         :: "r"(s0 + r * 256 * 16), "l"(p + r * 256 + tid));
        }
        asm volatile("cp.async.commit_group;");
        asm volatile("cp.async.wait_group 0;" ::: "memory");
    }
    __syncthreads();

    const bool up1 = (lane >> 1) & 1;
    const bool up2 = (lane >> 2) & 1;
    const bool up3 = (lane >> 3) & 1;
    const int  o_of_lane = 8 * (lane & 1) + 4 * ((lane >> 1) & 1) +
                           2 * ((lane >> 2) & 1) + ((lane >> 3) & 1);

    for (int it = 0; it < 3; it++) {
        float S[8], z = 0.0f;
        u64 S2[4] = {0ull, 0ull, 0ull, 0ull};
        if (it == 0) {
#pragma unroll
            for (int r = 0; r < 9; r++) {
                uint4 t = slab[r * 256 + tid];
                S2[0] = add2(S2[0], h2f2(t.x));
                S2[1] = add2(S2[1], h2f2(t.y));
                S2[2] = add2(S2[2], h2f2(t.z));
                S2[3] = add2(S2[3], h2f2(t.w));
            }
        } else {
            u64 V2[4];
#pragma unroll
            for (int k = 0; k < 4; k++)
                V2[k] = pack2(Vs[8 * h + 2 * k], Vs[8 * h + 2 * k + 1]);
#pragma unroll
            for (int r = 0; r < 9; r++) {
                uint4 t = slab[r * 256 + tid];
                u64 f0 = h2f2(t.x), f1 = h2f2(t.y);
                u64 f2 = h2f2(t.z), f3 = h2f2(t.w);
                u64 d = mul2(f0, V2[0]);
                d = fma2(f1, V2[1], d);
                d = fma2(f2, V2[2], d);
                d = fma2(f3, V2[3], d);
                float lo, hi; unpack2(d, lo, hi);
                float a = lo + hi;
                a += __shfl_xor_sync(0xffffffffu, a, 1);  // partner o-half
                float e = __expf(a);
                z += e;
                u64 ed = dup2(e);
                S2[0] = fma2(ed, f0, S2[0]);
                S2[1] = fma2(ed, f1, S2[1]);
                S2[2] = fma2(ed, f2, S2[2]);
                S2[3] = fma2(ed, f3, S2[3]);
            }
        }
#pragma unroll
        for (int k = 0; k < 4; k++) unpack2(S2[k], S[2 * k], S[2 * k + 1]);

        // --- split-butterfly S-reduce over the 16 same-half lanes ---
        float v4[4];
#pragma unroll
        for (int k = 0; k < 4; k++) {
            float send = up1 ? S[k] : S[k + 4];
            float recv = __shfl_xor_sync(0xffffffffu, send, 2);
            v4[k] = (up1 ? S[k + 4] : S[k]) + recv;
        }
        float v2[2];
#pragma unroll
        for (int k = 0; k < 2; k++) {
            float send = up2 ? v4[k] : v4[k + 2];
            float recv = __shfl_xor_sync(0xffffffffu, send, 4);
            v2[k] = (up2 ? v4[k + 2] : v4[k]) + recv;
        }
        float v1;
        {
            float send = up3 ? v2[0] : v2[1];
            float recv = __shfl_xor_sync(0xffffffffu, send, 8);
            v1 = (up3 ? v2[1] : v2[0]) + recv;
        }
        v1 += __shfl_xor_sync(0xffffffffu, v1, 16);
        // v1 = S_total[o_of_lane], lanes 0..15 cover all o uniquely

        // z tree over the 16 same-parity lanes (it>0 only)
        if (it > 0) {
#pragma unroll
            for (int off = 2; off <= 16; off <<= 1)
                z += __shfl_xor_sync(0xffffffffu, z, off);
        }

        if (lane < 16) red[wid][o_of_lane] = v1;
        if (lane == 0) red[wid][16] = z;
        __syncthreads();

        // Final combine + squash: 16 threads, one per o
        if (tid < 16) {
            int o = tid;
            float s = 0.0f, Z = 0.0f;
#pragma unroll
            for (int w = 0; w < 8; w++) { s += red[w][o]; Z += red[w][16]; }
            if (it == 0) Z = (float)Nn;  // softmax of zeros: Z exactly N
            s /= Z;
            float sn = s * s;
#pragma unroll
            for (int off = 1; off <= 8; off <<= 1)
                sn += __shfl_xor_sync(0xffffu, sn, off);
            float fq = (sn / (1.0f + sn)) * rsqrtf(sn);
            float v = s * fq;
            if (it == 2) out[((size_t)c * Bb + b) * Oo + o] = v;
            else Vs[o] = (it == 0) ? v : (Vs[o] + v);
        }
        __syncthreads();
    }
}

// ---------------------------------------------------------------------------
extern "C" void kernel_launch(void* const* d_in, const int* in_sizes, int n_in,
                              void* d_out, int out_size) {
    const float* u = (const float*)d_in[0];  // [B,N,I]
    const float* W = (const float*)d_in[1];  // [C,N,I,O]
    float* out = (float*)d_out;              // [C,B,1,1,O]

    uhat_kernel<<<dim3(Nn / 128, Bb / 32, Cc / 2), 256>>>(u, W);
    routing_kernel<<<dim3(Bb, Cc), 256>>>(out);
}